// round 16
// baseline (speedup 1.0000x reference)
#include <cuda_runtime.h>
#include <math.h>

#define NBATCH 8
#define DPIX   147456     // 384*384
#define KB     256
#define BINS   50
#define PSTR   (NBATCH * BINS * KB)   // P partial stride
#define QSTR   (NBATCH * KB)          // Q partial stride

// Scratch (device globals; no dynamic allocation allowed)
__device__ __align__(16) float g_A[NBATCH * KB * KB];    // fine 2D histogram (2 MB, memset node)
__device__ __align__(16) float g_GT[KB * BINS];           // GT[i][b]
__device__ __align__(16) float g_GS[KB];                  // GS[i] = sum_b G[b][i] (telescoped)
__device__ __align__(16) float g_P [4 * PSTR];            // P partials [is][n][b][j]
__device__ __align__(16) float g_Q [4 * QSTR];            // Q partials [is][n][j]
__device__ __align__(16) float g_myS[NBATCH * BINS];      // col marginals
__device__ __align__(16) float g_Spart[NBATCH];           // per-n totals
__device__ unsigned int g_cntQ[NBATCH];                   // per-n Q-producer counters (self-reset)

// ---------------- Kernel 1: nearest-cell 2D histogram + GT/GS + out zero ------
__device__ __forceinline__ void red1(float* p, float a) {
    asm volatile("red.global.add.f32 [%0], %1;" :: "l"(p), "f"(a) : "memory");
}

__global__ void k_hist(const float* __restrict__ im1, const float* __restrict__ im2,
                       float* __restrict__ out) {
    int gid = blockIdx.x * blockDim.x + threadIdx.x;   // one float4 chunk (4 pixels)

    if (gid == 0) out[0] = 0.0f;                       // harness poisons d_out

    if (gid < BINS * KB) {
        int b = gid / KB, i = gid % KB;
        float x = (i + 0.5f) * (1.0f / KB);
        float c = (b + 0.5f) * 0.02f;
        float d = 10.0f * (x - c);
        float s1 = 1.0f / (1.0f + __expf(-(d + 0.1f)));
        float s2 = 1.0f / (1.0f + __expf(-(d - 0.1f)));
        g_GT[i * BINS + b] = s1 - s2;
        if (b == 0) {   // GS[i] = sum_b G[b][i], telescoped closed form
            float t1 = 1.0f / (1.0f + __expf(-10.0f * x));
            float t2 = 1.0f / (1.0f + __expf(-10.0f * (x - 1.0f)));
            g_GS[i] = t1 - t2;
        }
    }

    const int nchunk = (NBATCH * DPIX) / 4;
    if (gid >= nchunk) return;
    int n = gid / (DPIX / 4);   // 36864 chunks per batch, no straddle
    float4 xv = ((const float4*)im1)[gid];
    float4 yv = ((const float4*)im2)[gid];
    float* base = g_A + (size_t)n * KB * KB;

    float xs[4] = {xv.x, xv.y, xv.z, xv.w};
    float ys[4] = {yv.x, yv.y, yv.z, yv.w};
#pragma unroll
    for (int q = 0; q < 4; q++) {
        int i0 = min(KB - 1, (int)(xs[q] * 256.0f));
        int j0 = min(KB - 1, (int)(ys[q] * 256.0f));
        red1(base + i0 * KB + j0, 1.0f);
    }
}

// ---------------- Kernel 2: P partials (+ Q row) + per-n my/S tail ------------
// grid = 8(n) * 2(jt) * 5(bg: 10 b) * 4(is: 64 i) = 320 blocks, 128 threads
__global__ void __launch_bounds__(128) k_stageC() {
    int blk = blockIdx.x;
    int n  = blk / 40;
    int r  = blk % 40;
    int jt = r / 20;
    int r2 = r % 20;
    int bg = r2 / 4, is = r2 % 4;
    int j  = jt * 128 + threadIdx.x;
    int b0 = bg * 10;
    int it = is * 64;
    int tid = threadIdx.x;

    __shared__ float Gs[64][12];   // cols 0-9: G rows; col 10: GS; col 11 pad
    float acc[10];
#pragma unroll
    for (int k = 0; k < 10; k++) acc[k] = 0.0f;
    float accQ = 0.0f;

    const float* A = g_A + (size_t)n * KB * KB + j;

    for (int t = tid; t < 640; t += 128) {
        int ii = t / 10, k = t % 10;
        Gs[ii][k] = g_GT[(it + ii) * BINS + b0 + k];
    }
    if (tid < 64) Gs[tid][10] = g_GS[it + tid];
    __syncthreads();
#pragma unroll 8
    for (int ii = 0; ii < 64; ii++) {
        float h = A[(size_t)(it + ii) * KB];
        float4 ga = *(const float4*)&Gs[ii][0];
        float4 gb = *(const float4*)&Gs[ii][4];
        float2 gc = *(const float2*)&Gs[ii][8];
        acc[0] += h * ga.x; acc[1] += h * ga.y; acc[2] += h * ga.z; acc[3] += h * ga.w;
        acc[4] += h * gb.x; acc[5] += h * gb.y; acc[6] += h * gb.z; acc[7] += h * gb.w;
        acc[8] += h * gc.x; acc[9] += h * gc.y;
        accQ   += h * Gs[ii][10];
    }

    size_t pb = (size_t)is * PSTR + ((size_t)(n * BINS + b0)) * KB + j;
#pragma unroll
    for (int k = 0; k < 10; k++) g_P[pb + (size_t)k * KB] = acc[k];

    if (bg != 0) return;
    g_Q[(size_t)is * QSTR + (size_t)n * KB + j] = accQ;

    // ---- per-n tail: last of the 8 Q-producing blocks computes my + Spart ----
    __threadfence();
    __syncthreads();
    __shared__ bool isLast;
    if (tid == 0) isLast = (atomicAdd(&g_cntQ[n], 1u) == 7u);
    __syncthreads();
    if (!isLast) return;
    if (tid == 0) g_cntQ[n] = 0;   // reset for next graph replay

    __shared__ float Qs[KB];
    __shared__ float part2[2][64];
    __shared__ float rows[64];
    for (int t = tid; t < KB; t += 128) {
        size_t base = (size_t)n * KB + t;
        Qs[t] = g_Q[base] + g_Q[QSTR + base] + g_Q[2 * (size_t)QSTR + base]
              + g_Q[3 * (size_t)QSTR + base];
    }
    __syncthreads();

    int g2 = tid >> 6, c2 = tid & 63;   // 2 j-halves of 128
    float s = 0.0f;
    if (c2 < BINS) {
        const float* GTc = g_GT + c2;
        int j0 = g2 * 128;
        float a0 = 0.f, a1 = 0.f, a2 = 0.f, a3 = 0.f;
#pragma unroll 8
        for (int jj = 0; jj < 128; jj += 4) {
            a0 += Qs[j0 + jj]     * GTc[(j0 + jj)     * BINS];
            a1 += Qs[j0 + jj + 1] * GTc[(j0 + jj + 1) * BINS];
            a2 += Qs[j0 + jj + 2] * GTc[(j0 + jj + 2) * BINS];
            a3 += Qs[j0 + jj + 3] * GTc[(j0 + jj + 3) * BINS];
        }
        s = (a0 + a1) + (a2 + a3);
    }
    part2[g2][c2] = s;
    __syncthreads();
    if (tid < 64) {
        float t = part2[0][tid] + part2[1][tid];
        if (tid < BINS) g_myS[n * BINS + tid] = t;
        rows[tid] = (tid < BINS) ? t : 0.0f;
    }
    __syncthreads();
    if (tid < 32) {
        float r3 = rows[tid] + rows[tid + 32];
#pragma unroll
        for (int o = 16; o; o >>= 1) r3 += __shfl_xor_sync(0xffffffffu, r3, o);
        if (tid == 0) g_Spart[n] = r3;
    }
}

// ---------------- Kernel 3: hgram rows + mx + MI terms (fused, smem GT) -------
// grid = 400 (nb = n*50+b), 512 threads: tid = g*64 + c, g in 0..7 (32-j dots)
__global__ void __launch_bounds__(512) k_stageD(float* __restrict__ out) {
    extern __shared__ float GTs[];    // [KB][BINS] = 50 KB dynamic
    int nb = blockIdx.x;
    int n  = nb / BINS;
    __shared__ float Ps[KB];
    __shared__ float part[8][64];
    __shared__ float rows[64];
    __shared__ float mired[64];
    __shared__ float sMx;
    int tid = threadIdx.x;
    int g = tid >> 6, c = tid & 63;

    // grand total (8 broadcast loads, issued early)
    float S = 0.0f;
#pragma unroll
    for (int k = 0; k < NBATCH; k++) S += g_Spart[k];

    // stage GT (12800 floats, coalesced) and Ps
    for (int t = tid; t < KB * BINS; t += 512) GTs[t] = g_GT[t];
    if (tid < KB) {
        size_t base = (size_t)nb * KB + tid;
        Ps[tid] = g_P[base] + g_P[PSTR + base] + g_P[2 * (size_t)PSTR + base]
                + g_P[3 * (size_t)PSTR + base];
    }
    __syncthreads();

    float s = 0.0f;
    if (c < BINS) {
        int j0 = g * 32;
        float a0 = 0.f, a1 = 0.f, a2 = 0.f, a3 = 0.f;
#pragma unroll
        for (int j = 0; j < 32; j += 4) {
            a0 += Ps[j0 + j]     * GTs[(j0 + j)     * BINS + c];
            a1 += Ps[j0 + j + 1] * GTs[(j0 + j + 1) * BINS + c];
            a2 += Ps[j0 + j + 2] * GTs[(j0 + j + 2) * BINS + c];
            a3 += Ps[j0 + j + 3] * GTs[(j0 + j + 3) * BINS + c];
        }
        s = (a0 + a1) + (a2 + a3);
    }
    part[g][c] = s;
    __syncthreads();

    float t = 0.0f;
    if (tid < 64) {
        t = ((part[0][tid] + part[1][tid]) + (part[2][tid] + part[3][tid]))
          + ((part[4][tid] + part[5][tid]) + (part[6][tid] + part[7][tid]));
        rows[tid] = (tid < BINS) ? t : 0.0f;
    }
    __syncthreads();
    if (tid < 32) {
        float r = rows[tid] + rows[tid + 32];
#pragma unroll
        for (int o = 16; o; o >>= 1) r += __shfl_xor_sync(0xffffffffu, r, o);
        if (tid == 0) sMx = r;
    }
    __syncthreads();

    // MI terms for this row
    float mi = 0.0f;
    if (tid < BINS) {
        float inv = 1.0f / S;
        float p = t * inv;
        float q = (sMx * inv) * (g_myS[n * BINS + tid] * inv);
        mi = p * __logf(__fdividef(p + 1e-8f, q + 1e-8f));
    }
    if (tid < 64) mired[tid] = mi;
    __syncthreads();
    if (tid < 32) {
        float m = mired[tid] + mired[tid + 32];
#pragma unroll
        for (int o = 16; o; o >>= 1) m += __shfl_xor_sync(0xffffffffu, m, o);
        if (tid == 0) atomicAdd(out, m);
    }
}

// ---------------- Launch -------------------------------------------------------
extern "C" void kernel_launch(void* const* d_in, const int* in_sizes, int n_in,
                              void* d_out, int out_size) {
    const float* im1 = (const float*)d_in[0];
    const float* im2 = (const float*)d_in[1];

    static bool attrDone = false;
    if (!attrDone) {
        cudaFuncSetAttribute(k_stageD, cudaFuncAttributeMaxDynamicSharedMemorySize,
                             KB * BINS * (int)sizeof(float));
        attrDone = true;
    }

    void* aPtr = nullptr;
    cudaGetSymbolAddress(&aPtr, g_A);
    cudaMemsetAsync(aPtr, 0, sizeof(float) * NBATCH * KB * KB);

    k_hist  <<<(NBATCH * DPIX / 4 + 255) / 256, 256>>>(im1, im2, (float*)d_out);
    k_stageC<<<320, 128>>>();
    k_stageD<<<400, 512, KB * BINS * sizeof(float)>>>((float*)d_out);
}

// round 17
// speedup vs baseline: 1.1110x; 1.1110x over previous
#include <cuda_runtime.h>
#include <math.h>

#define NBATCH 8
#define DPIX   147456     // 384*384
#define KB     256
#define BINS   50
#define PSTR   (NBATCH * BINS * KB)   // P partial stride
#define QSTR   (NBATCH * KB)          // Q partial stride

// Scratch (device globals; no dynamic allocation allowed)
// g_A starts zeroed at module load; k_stageD re-zeroes it each run so every
// graph replay sees the all-zero invariant without a memset node.
__device__ __align__(16) float g_A[NBATCH * KB * KB];    // fine 2D histogram (2 MB)
__device__ __align__(16) float g_GT[KB * BINS];           // GT[i][b]
__device__ __align__(16) float g_GS[KB];                  // GS[i] = sum_b G[b][i] (telescoped)
__device__ __align__(16) float g_P [4 * PSTR];            // P partials [is][n][b][j]
__device__ __align__(16) float g_Q [4 * QSTR];            // Q partials [is][n][j]
__device__ __align__(16) float g_myS[NBATCH * BINS];      // col marginals
__device__ __align__(16) float g_Spart[NBATCH];           // per-n totals

// ---------------- Kernel 1: nearest-cell 2D histogram + GT/GS + out zero ------
__device__ __forceinline__ void red1(float* p, float a) {
    asm volatile("red.global.add.f32 [%0], %1;" :: "l"(p), "f"(a) : "memory");
}

__global__ void k_hist(const float* __restrict__ im1, const float* __restrict__ im2,
                       float* __restrict__ out) {
    int gid = blockIdx.x * blockDim.x + threadIdx.x;   // one float4 chunk (4 pixels)

    if (gid == 0) out[0] = 0.0f;                       // harness poisons d_out

    if (gid < BINS * KB) {
        int b = gid / KB, i = gid % KB;
        float x = (i + 0.5f) * (1.0f / KB);
        float c = (b + 0.5f) * 0.02f;
        float d = 10.0f * (x - c);
        float s1 = 1.0f / (1.0f + __expf(-(d + 0.1f)));
        float s2 = 1.0f / (1.0f + __expf(-(d - 0.1f)));
        g_GT[i * BINS + b] = s1 - s2;
        if (b == 0) {   // GS[i] = sum_b G[b][i], telescoped closed form
            float t1 = 1.0f / (1.0f + __expf(-10.0f * x));
            float t2 = 1.0f / (1.0f + __expf(-10.0f * (x - 1.0f)));
            g_GS[i] = t1 - t2;
        }
    }

    const int nchunk = (NBATCH * DPIX) / 4;
    if (gid >= nchunk) return;
    int n = gid / (DPIX / 4);   // 36864 chunks per batch, no straddle
    float4 xv = ((const float4*)im1)[gid];
    float4 yv = ((const float4*)im2)[gid];
    float* base = g_A + (size_t)n * KB * KB;

    float xs[4] = {xv.x, xv.y, xv.z, xv.w};
    float ys[4] = {yv.x, yv.y, yv.z, yv.w};
#pragma unroll
    for (int q = 0; q < 4; q++) {
        int i0 = min(KB - 1, (int)(xs[q] * 256.0f));
        int j0 = min(KB - 1, (int)(ys[q] * 256.0f));
        red1(base + i0 * KB + j0, 1.0f);
    }
}

// ---------------- Kernel 2: P[is][n][b][j] (+ Q row), 4-way i-split -----------
// grid = 8(n) * 2(jt) * 5(bg: 10 b) * 4(is: 64 i) = 320 blocks, 128 threads
__global__ void __launch_bounds__(128) k_stageC() {
    int blk = blockIdx.x;
    int n  = blk / 40;
    int r  = blk % 40;
    int jt = r / 20;
    int r2 = r % 20;
    int bg = r2 / 4, is = r2 % 4;
    int j  = jt * 128 + threadIdx.x;
    int b0 = bg * 10;
    int it = is * 64;

    __shared__ float Gs[64][12];   // cols 0-9: G rows; col 10: GS; col 11 pad
    float acc[10];
#pragma unroll
    for (int k = 0; k < 10; k++) acc[k] = 0.0f;
    float accQ = 0.0f;

    const float* A = g_A + (size_t)n * KB * KB + j;

    for (int t = threadIdx.x; t < 640; t += 128) {
        int ii = t / 10, k = t % 10;
        Gs[ii][k] = g_GT[(it + ii) * BINS + b0 + k];
    }
    if (threadIdx.x < 64) Gs[threadIdx.x][10] = g_GS[it + threadIdx.x];
    __syncthreads();
#pragma unroll 8
    for (int ii = 0; ii < 64; ii++) {
        float h = A[(size_t)(it + ii) * KB];
        float4 ga = *(const float4*)&Gs[ii][0];
        float4 gb = *(const float4*)&Gs[ii][4];
        float2 gc = *(const float2*)&Gs[ii][8];
        acc[0] += h * ga.x; acc[1] += h * ga.y; acc[2] += h * ga.z; acc[3] += h * ga.w;
        acc[4] += h * gb.x; acc[5] += h * gb.y; acc[6] += h * gb.z; acc[7] += h * gb.w;
        acc[8] += h * gc.x; acc[9] += h * gc.y;
        accQ   += h * Gs[ii][10];
    }

    size_t pb = (size_t)is * PSTR + ((size_t)(n * BINS + b0)) * KB + j;
#pragma unroll
    for (int k = 0; k < 10; k++) g_P[pb + (size_t)k * KB] = acc[k];
    if (bg == 0) g_Q[(size_t)is * QSTR + (size_t)n * KB + j] = accQ;
}

// ---------------- Kernel 3: my[n][c] + Spart[n] --------------------------------
// grid = 8 (n), 256 threads: tid = g*64 + c
__global__ void __launch_bounds__(256) k_my() {
    int n = blockIdx.x;
    __shared__ float Qs[KB];
    __shared__ float part[4][64];
    __shared__ float rows[64];
    int tid = threadIdx.x;
    int g = tid >> 6, c = tid & 63;

    Qs[tid] = g_Q[(size_t)n * KB + tid]
            + g_Q[(size_t)QSTR     + n * KB + tid]
            + g_Q[(size_t)QSTR * 2 + n * KB + tid]
            + g_Q[(size_t)QSTR * 3 + n * KB + tid];
    __syncthreads();

    float s = 0.0f;
    if (c < BINS) {
        const float* GTc = g_GT + c;
        int j0 = g * 64;
        float a0 = 0.f, a1 = 0.f, a2 = 0.f, a3 = 0.f;
#pragma unroll
        for (int j = 0; j < 64; j += 4) {
            a0 += Qs[j0 + j]     * GTc[(j0 + j)     * BINS];
            a1 += Qs[j0 + j + 1] * GTc[(j0 + j + 1) * BINS];
            a2 += Qs[j0 + j + 2] * GTc[(j0 + j + 2) * BINS];
            a3 += Qs[j0 + j + 3] * GTc[(j0 + j + 3) * BINS];
        }
        s = (a0 + a1) + (a2 + a3);
    }
    part[g][c] = s;
    __syncthreads();

    if (tid < 64) {
        float t = (part[0][tid] + part[1][tid]) + (part[2][tid] + part[3][tid]);
        if (tid < BINS) g_myS[n * BINS + tid] = t;
        rows[tid] = (tid < BINS) ? t : 0.0f;
    }
    __syncthreads();
    if (tid < 32) {
        float r = rows[tid] + rows[tid + 32];
#pragma unroll
        for (int o = 16; o; o >>= 1) r += __shfl_xor_sync(0xffffffffu, r, o);
        if (tid == 0) g_Spart[n] = r;
    }
}

// ---------------- Kernel 4: hgram rows + mx + MI terms + g_A re-zero ----------
// grid = 400 (nb = n*50+b), 512 threads: tid = g*64 + c, g in 0..7 (32-j dots)
__global__ void __launch_bounds__(512) k_stageD(float* __restrict__ out) {
    int nb = blockIdx.x;
    int n  = nb / BINS;
    __shared__ float Ps[KB];
    __shared__ float part[8][64];
    __shared__ float rows[64];
    __shared__ float mired[64];
    __shared__ float sMx;
    int tid = threadIdx.x;
    int g = tid >> 6, c = tid & 63;

    // re-zero g_A for the next replay (runs after stageC, the only reader).
    // 131072 float4s over 400*512 threads: one per thread, grid-strided once.
    {
        int idx = nb * 512 + tid;
        if (idx < (NBATCH * KB * KB) / 4)
            ((float4*)g_A)[idx] = make_float4(0.f, 0.f, 0.f, 0.f);
    }

    // grand total (8 broadcast loads, issued early)
    float S = 0.0f;
#pragma unroll
    for (int k = 0; k < NBATCH; k++) S += g_Spart[k];

    if (tid < KB) {
        size_t base = (size_t)nb * KB + tid;
        Ps[tid] = g_P[base] + g_P[PSTR + base] + g_P[2 * (size_t)PSTR + base]
                + g_P[3 * (size_t)PSTR + base];
    }
    __syncthreads();

    float s = 0.0f;
    if (c < BINS) {
        const float* GTc = g_GT + c;
        int j0 = g * 32;
        float a0 = 0.f, a1 = 0.f, a2 = 0.f, a3 = 0.f;
#pragma unroll
        for (int j = 0; j < 32; j += 4) {
            a0 += Ps[j0 + j]     * GTc[(j0 + j)     * BINS];
            a1 += Ps[j0 + j + 1] * GTc[(j0 + j + 1) * BINS];
            a2 += Ps[j0 + j + 2] * GTc[(j0 + j + 2) * BINS];
            a3 += Ps[j0 + j + 3] * GTc[(j0 + j + 3) * BINS];
        }
        s = (a0 + a1) + (a2 + a3);
    }
    part[g][c] = s;
    __syncthreads();

    float t = 0.0f;
    if (tid < 64) {
        t = ((part[0][tid] + part[1][tid]) + (part[2][tid] + part[3][tid]))
          + ((part[4][tid] + part[5][tid]) + (part[6][tid] + part[7][tid]));
        rows[tid] = (tid < BINS) ? t : 0.0f;
    }
    __syncthreads();
    if (tid < 32) {
        float r = rows[tid] + rows[tid + 32];
#pragma unroll
        for (int o = 16; o; o >>= 1) r += __shfl_xor_sync(0xffffffffu, r, o);
        if (tid == 0) sMx = r;
    }
    __syncthreads();

    // MI terms for this row
    float mi = 0.0f;
    if (tid < BINS) {
        float inv = 1.0f / S;
        float p = t * inv;
        float q = (sMx * inv) * (g_myS[n * BINS + tid] * inv);
        mi = p * __logf(__fdividef(p + 1e-8f, q + 1e-8f));
    }
    if (tid < 64) mired[tid] = mi;
    __syncthreads();
    if (tid < 32) {
        float m = mired[tid] + mired[tid + 32];
#pragma unroll
        for (int o = 16; o; o >>= 1) m += __shfl_xor_sync(0xffffffffu, m, o);
        if (tid == 0) atomicAdd(out, m);
    }
}

// ---------------- Launch -------------------------------------------------------
extern "C" void kernel_launch(void* const* d_in, const int* in_sizes, int n_in,
                              void* d_out, int out_size) {
    const float* im1 = (const float*)d_in[0];
    const float* im2 = (const float*)d_in[1];

    k_hist  <<<(NBATCH * DPIX / 4 + 255) / 256, 256>>>(im1, im2, (float*)d_out);
    k_stageC<<<320, 128>>>();
    k_my    <<<8, 256>>>();
    k_stageD<<<400, 512>>>((float*)d_out);
}